// round 7
// baseline (speedup 1.0000x reference)
#include <cuda_runtime.h>

// DispCorrM: out[b,d,h,w] = (1/C) * sum_c L[b,c,h,w] * R[b,c,h,w-d]   (0 if w<d)
// x: (B, 2C, H, W) fp32, L = x[:, :C], R = x[:, C:]
// Fixed shapes: B=4, C=32, H=256, W=512, D=64.
//
// R7: R5 structure (NW=4, ND=16, TW=128, cp.async double-buffer, immediate-
// offset LDS) with the mainloop rebuilt on packed fma.rn.f32x2:
//   - acc packed along w: acc01=(w0,w1), acc23=(w2,w3)
//   - b-operand pairs hoisted per channel: E[j] free from float4 loads,
//     O[j] built once (alu pipe) and reused across all 16 d's.
// FFMA-pipe residency halves (64 -> 32 slots/warp-channel); LDS crossbar
// (24 cyc/warp-channel) becomes the binding floor.

#define BB 4
#define CC 32
#define HH 256
#define WW 512
#define DD 64

#define TW 128           // w-tile per block
#define RW (64 + TW)     // R tile width incl. 64-col left halo/zero-pad
#define ND 16            // d's per thread (per warp)
#define NW 4             // w's per thread
#define CH 16            // channels per chunk (2 chunks, double-buffered)

typedef float4 f4;
typedef unsigned long long ull;

__device__ __forceinline__ void cp_async16(unsigned smem_addr, const void* gptr) {
    asm volatile("cp.async.cg.shared.global [%0], [%1], 16;\n"
                 :: "r"(smem_addr), "l"(gptr));
}
__device__ __forceinline__ void cp_commit() {
    asm volatile("cp.async.commit_group;\n");
}
template <int N>
__device__ __forceinline__ void cp_wait() {
    asm volatile("cp.async.wait_group %0;\n" :: "n"(N));
}

__device__ __forceinline__ ull pack2(float lo, float hi) {
    ull v;
    asm("mov.b64 %0, {%1, %2};" : "=l"(v) : "f"(lo), "f"(hi));
    return v;
}
__device__ __forceinline__ void fma2(ull& acc, ull a, ull b) {
    asm("fma.rn.f32x2 %0, %1, %2, %0;" : "+l"(acc) : "l"(a), "l"(b));
}
__device__ __forceinline__ void unpack2(ull v, float& lo, float& hi) {
    asm("mov.b64 {%0, %1}, %2;" : "=f"(lo), "=f"(hi) : "l"(v));
}

__global__ __launch_bounds__(128, 4)
void disp_corr_kernel(const float* __restrict__ x, float* __restrict__ out) {
    __shared__ float Lsh[2][CH][TW];   // 2 x 8 KB
    __shared__ float Rsh[2][CH][RW];   // 2 x 12 KB

    const int tile = blockIdx.x;            // 0..3
    const int h    = blockIdx.y;            // 0..255
    const int b    = blockIdx.z;            // 0..3
    const int tile_start = tile * TW;
    const int tid = threadIdx.x;

    const size_t HW = (size_t)HH * WW;

    const float* Lg = x + ((size_t)(b * 2 * CC) * HH + h) * WW + tile_start;
    const float* Rg = x + ((size_t)(b * 2 * CC + CC) * HH + h) * WW;

    // ---- async chunk loader: channels [ck*CH, ck*CH+CH) -> buffer ck ----
    auto load_chunk = [&](int ck) {
        const int c0 = ck * CH;
        #pragma unroll
        for (int k = 0; k < (CH * TW / 4) / 128; k++) {
            int idx = k * 128 + tid;
            int c  = idx / (TW / 4);
            int w4 = idx % (TW / 4);
            unsigned sa = (unsigned)__cvta_generic_to_shared(&Lsh[ck][c][4 * w4]);
            cp_async16(sa, Lg + (size_t)(c0 + c) * HW + 4 * w4);
        }
        #pragma unroll
        for (int k = 0; k < (CH * (RW / 4)) / 128; k++) {
            int idx = k * 128 + tid;
            int c  = idx / (RW / 4);
            int j4 = idx % (RW / 4);
            int wg = tile_start + 4 * j4 - 64;
            if (wg >= 0) {
                unsigned sa = (unsigned)__cvta_generic_to_shared(&Rsh[ck][c][4 * j4]);
                cp_async16(sa, Rg + (size_t)(c0 + c) * HW + wg);
            } else {
                *(f4*)&Rsh[ck][c][4 * j4] = make_float4(0.f, 0.f, 0.f, 0.f);
            }
        }
        cp_commit();
    };

    load_chunk(0);   // group 0 in flight

    const int lane = tid & 31;
    const int warp = tid >> 5;            // 0..3
    const int w0 = lane * 4;              // 16B lane stride: conflict-free LDS.128
    const int d0 = warp * ND;             // 0,16,32,48

    // Packed accumulators: acc01[dd]=(acc_w0,acc_w1), acc23[dd]=(acc_w2,acc_w3)
    ull acc01[ND], acc23[ND];
    #pragma unroll
    for (int i = 0; i < ND; i++) { acc01[i] = 0ULL; acc23[i] = 0ULL; }

    // R window float index for (w0+i, d0+dd): r[k], k = 16 - dd + i, window r[0..19]
    const int rbase = 64 + w0 - d0 - 16;   // multiple of 4

    auto compute_chunk = [&](int ck) {
        const f4* lp = (const f4*)&Lsh[ck][0][w0];      // + c*(TW/4)
        const f4* rp = (const f4*)&Rsh[ck][0][rbase];   // + c*(RW/4) + q

        #pragma unroll
        for (int c = 0; c < CH; c++) {
            f4 Lv = lp[c * (TW / 4)];
            ull La = pack2(Lv.x, Lv.y);     // (L[w0],L[w0+1]) — aligned, free
            ull Lb = pack2(Lv.z, Lv.w);

            float r[20];
            #pragma unroll
            for (int q = 0; q < 5; q++)
                *(f4*)&r[4 * q] = rp[c * (RW / 4) + q];

            // Even pairs: free (aligned halves of the float4 loads).
            ull E[10];
            #pragma unroll
            for (int j = 0; j < 10; j++) E[j] = pack2(r[2 * j], r[2 * j + 1]);
            // Odd pairs: built once per channel, reused across all 16 dd.
            ull O[9];
            #pragma unroll
            for (int j = 0; j < 9; j++) O[j] = pack2(r[2 * j + 1], r[2 * j + 2]);

            #pragma unroll
            for (int dd = 0; dd < ND; dd++) {
                // acc01 needs (r[16-dd], r[17-dd]); acc23 needs (r[18-dd], r[19-dd])
                if ((dd & 1) == 0) {
                    fma2(acc01[dd], La, E[(16 - dd) >> 1]);
                    fma2(acc23[dd], Lb, E[(18 - dd) >> 1]);
                } else {
                    fma2(acc01[dd], La, O[(15 - dd) >> 1]);
                    fma2(acc23[dd], Lb, O[(17 - dd) >> 1]);
                }
            }
        }
    };

    // Pipeline: start chunk 1 loads, compute chunk 0 under them, then chunk 1.
    load_chunk(1);   // group 1 in flight
    cp_wait<1>();    // chunk 0 landed
    __syncthreads();
    compute_chunk(0);
    cp_wait<0>();    // chunk 1 landed
    __syncthreads();
    compute_chunk(1);

    // ---- Epilogue: scale by 1/C and store (float4, contiguous per warp) ----
    const float inv_c = 1.0f / (float)CC;
    float* og = out + (((size_t)b * DD + d0) * HH + h) * WW + tile_start + w0;
    #pragma unroll
    for (int dd = 0; dd < ND; dd++) {
        float a0, a1, a2, a3;
        unpack2(acc01[dd], a0, a1);
        unpack2(acc23[dd], a2, a3);
        f4 v = make_float4(a0 * inv_c, a1 * inv_c, a2 * inv_c, a3 * inv_c);
        *(f4*)(og + (size_t)dd * HW) = v;
    }
}

extern "C" void kernel_launch(void* const* d_in, const int* in_sizes, int n_in,
                              void* d_out, int out_size) {
    const float* x = (const float*)d_in[0];
    float* out = (float*)d_out;
    dim3 grid(WW / TW, HH, BB);   // (4, 256, 4) = 4096 blocks
    disp_corr_kernel<<<grid, 128>>>(x, out);
}

// round 8
// speedup vs baseline: 1.0731x; 1.0731x over previous
#include <cuda_runtime.h>
#include <cstdint>

// DispCorrM via banded tf32 mma.sync (HMMA) GEMM.
// out[b,d,h,w] = (1/32) * sum_c L[c,w] * R[c,w-d]   (0 if w<d)
// Per CTA (b, h, w-tile of 128): D[m,n] = sum_c A[m,c]*B[n,c]
//   A[m,c] = L[c, w0+m]   (128 x 32)
//   B[n,c] = R[c, w0-64+n] (192 x 32, zero for w<0)
//   out[d, w0+m] = D[m, m+64-d]/32
// Band: per m16-tile mt only n in [16mt, 16mt+80) is needed (10 n8-tiles).
// Shapes fixed: B=4, C=32, H=256, W=512, D=64.

#define BB    4
#define CCH   32
#define HH    256
#define WW    512
#define DDISP 64
#define HW    ((size_t)HH * WW)

#define PAD  36     // floats per smem operand row: (4g+t) bank-distinct fragment LDS
#define OPAD 132    // floats per staging row: conflict-free band STS

__device__ __forceinline__ uint32_t f2tf32(float v) {
    uint32_t t;
    asm("cvt.rna.tf32.f32 %0, %1;" : "=r"(t) : "f"(v));
    return t;
}

__device__ __forceinline__ void mma8(float* c, const uint32_t* a, uint32_t b0, uint32_t b1) {
    asm volatile(
        "mma.sync.aligned.m16n8k8.row.col.f32.tf32.tf32.f32 "
        "{%0,%1,%2,%3}, {%4,%5,%6,%7}, {%8,%9}, {%0,%1,%2,%3};"
        : "+f"(c[0]), "+f"(c[1]), "+f"(c[2]), "+f"(c[3])
        : "r"(a[0]), "r"(a[1]), "r"(a[2]), "r"(a[3]), "r"(b0), "r"(b1));
}

__global__ __launch_bounds__(128, 4)
void disp_corr_mma_kernel(const float* __restrict__ x, float* __restrict__ out) {
    __shared__ union {
        struct {
            uint32_t A[128 * PAD];   // tf32 bit patterns, 18 KB
            uint32_t B[192 * PAD];   // 27 KB
        } in;
        float O[DDISP * OPAD];       // 33 KB staging (aliased after mainloop)
    } sm;

    const int tid  = threadIdx.x;
    const int lane = tid & 31;
    const int warp = tid >> 5;          // 0..3
    const int tile = blockIdx.x;        // 0..3
    const int h    = blockIdx.y;
    const int b    = blockIdx.z;
    const int w0   = tile * 128;

    // ---- Load + transpose + tf32-convert into smem ----
    const float* Lg = x + (((size_t)b * 2 * CCH) * HH + h) * WW + w0;   // L[c][w0+m] at c*HW+m
    const float* Rg = x + (((size_t)b * 2 * CCH + CCH) * HH + h) * WW;  // R[c][w]    at c*HW+w

    {   // A row m = tid: 32 coalesced LDG (lane = w), STS to row m
        uint32_t* Ar = &sm.in.A[tid * PAD];
        #pragma unroll
        for (int c = 0; c < 32; c++)
            Ar[c] = f2tf32(__ldg(Lg + (size_t)c * HW + tid));
    }
    {   // B rows n = tid and n = 128+tid (tid<64)
        uint32_t* Br = &sm.in.B[tid * PAD];
        int wg = w0 - 64 + tid;
        if (wg >= 0) {
            #pragma unroll
            for (int c = 0; c < 32; c++)
                Br[c] = f2tf32(__ldg(Rg + (size_t)c * HW + wg));
        } else {
            #pragma unroll
            for (int c = 0; c < 32; c++) Br[c] = 0u;
        }
        if (tid < 64) {
            uint32_t* Br2 = &sm.in.B[(128 + tid) * PAD];
            int wg2 = w0 + 64 + tid;    // always >= 0
            #pragma unroll
            for (int c = 0; c < 32; c++)
                Br2[c] = f2tf32(__ldg(Rg + (size_t)c * HW + wg2));
        }
    }
    __syncthreads();

    // ---- Mainloop: warp owns m16-tiles {2w, 2w+1} (rows 32w..32w+31). ----
    // Their n-ranges [32w, 32w+80) and [32w+16, 32w+96) share B tiles j=0..11
    // (n_base = 32w + 8j): tile0 uses j=0..9, tile1 uses j=2..11.
    const int g = lane >> 2;            // 0..7
    const int t = lane & 3;             // 0..3
    const uint32_t* ap = &sm.in.A[(32 * warp + g) * PAD + t];
    const uint32_t* bp = &sm.in.B[(32 * warp + g) * PAD + t];

    float C0[10][4], C1[10][4];
    #pragma unroll
    for (int j = 0; j < 10; j++)
        #pragma unroll
        for (int r = 0; r < 4; r++) { C0[j][r] = 0.f; C1[j][r] = 0.f; }

    #pragma unroll
    for (int ks = 0; ks < 4; ks++) {
        uint32_t a0[4], a1[4];
        a0[0] = ap[8 * ks];                  a0[1] = ap[8 * PAD + 8 * ks];
        a0[2] = ap[8 * ks + 4];              a0[3] = ap[8 * PAD + 8 * ks + 4];
        a1[0] = ap[16 * PAD + 8 * ks];       a1[1] = ap[24 * PAD + 8 * ks];
        a1[2] = ap[16 * PAD + 8 * ks + 4];   a1[3] = ap[24 * PAD + 8 * ks + 4];

        #pragma unroll
        for (int j = 0; j < 12; j++) {
            uint32_t b0 = bp[j * 8 * PAD + 8 * ks];
            uint32_t b1 = bp[j * 8 * PAD + 8 * ks + 4];
            if (j < 10) mma8(C0[j], a0, b0, b1);
            if (j >= 2) mma8(C1[j - 2], a1, b0, b1);
        }
    }

    __syncthreads();   // all operand LDS done before aliasing smem as staging

    // ---- Band extraction into staging: d = row + 64 - 8j - col ----
    // C0: m = 32w + g (+8 for c2/c3); C1: m = 32w + 16 + g (+8). Same d formula.
    const float inv_c = 1.0f / 32.0f;
    #pragma unroll
    for (int half = 0; half < 2; half++) {
        const int mbase = 32 * warp + 16 * half + g;
        #pragma unroll
        for (int j = 0; j < 10; j++) {
            const float* Cr = half ? C1[j] : C0[j];
            const int dbase = g + 64 - 8 * j - 2 * t;
            if ((unsigned)dbase       < 64u) sm.O[dbase       * OPAD + mbase]     = Cr[0] * inv_c;
            if ((unsigned)(dbase - 1) < 64u) sm.O[(dbase - 1) * OPAD + mbase]     = Cr[1] * inv_c;
            if ((unsigned)(dbase + 8) < 64u) sm.O[(dbase + 8) * OPAD + mbase + 8] = Cr[2] * inv_c;
            if ((unsigned)(dbase + 7) < 64u) sm.O[(dbase + 7) * OPAD + mbase + 8] = Cr[3] * inv_c;
        }
    }
    __syncthreads();

    // ---- Coalesced store: warp handles d = warp + 4i, float4 per lane ----
    float* op = out + (((size_t)b * DDISP) * HH + h) * WW + w0;
    #pragma unroll
    for (int i = 0; i < 16; i++) {
        const int d = 4 * i + warp;
        float4 v = *(const float4*)&sm.O[d * OPAD + 4 * lane];
        *(float4*)(op + (size_t)d * HW + 4 * lane) = v;
    }
}

extern "C" void kernel_launch(void* const* d_in, const int* in_sizes, int n_in,
                              void* d_out, int out_size) {
    const float* x = (const float*)d_in[0];
    float* out = (float*)d_out;
    dim3 grid(WW / 128, HH, BB);   // (4, 256, 4) = 4096 blocks
    disp_corr_mma_kernel<<<grid, 128>>>(x, out);
}